// round 4
// baseline (speedup 1.0000x reference)
#include <cuda_runtime.h>
#include <cuda_bf16.h>
#include <cstdint>
#include <math.h>

#define NN 8192
#define FD 256
#define THETA   0.5f
#define ALPHA_S 0.2f

// ---------------- device global scratch ----------------
__device__ __nv_bfloat16 g_hhi[NN * FD];
__device__ __nv_bfloat16 g_hlo[NN * FD];
__device__ __nv_bfloat16 g_WThi[FD * FD];
__device__ __nv_bfloat16 g_WTlo[FD * FD];
__device__ __nv_bfloat16 g_WhThi[FD * NN];   // Wh^T [n][k]
__device__ __nv_bfloat16 g_WhTlo[FD * NN];
__device__ float g_f1[NN];
__device__ float g_f2[NN];

// ---------------- PTX helpers ----------------
__device__ __forceinline__ uint32_t smem_u32(const void* p) {
    uint32_t a;
    asm("{ .reg .u64 t; cvta.to.shared.u64 t, %1; cvt.u32.u64 %0, t; }"
        : "=r"(a) : "l"(p));
    return a;
}
__device__ __forceinline__ void cp_async16(uint32_t dst, const void* src) {
    asm volatile("cp.async.cg.shared.global [%0], [%1], 16;"
                 :: "r"(dst), "l"(src) : "memory");
}
__device__ __forceinline__ void cp_commit() {
    asm volatile("cp.async.commit_group;" ::: "memory");
}
template<int N>
__device__ __forceinline__ void cp_wait() {
    asm volatile("cp.async.wait_group %0;" :: "n"(N) : "memory");
}
__device__ __forceinline__ void ldm_x4(uint32_t addr, uint32_t& r0, uint32_t& r1,
                                       uint32_t& r2, uint32_t& r3) {
    asm volatile("ldmatrix.sync.aligned.m8n8.x4.shared.b16 {%0,%1,%2,%3}, [%4];"
                 : "=r"(r0), "=r"(r1), "=r"(r2), "=r"(r3) : "r"(addr));
}
__device__ __forceinline__ void mma_bf16(float* c, const uint32_t* a, const uint32_t* b) {
    asm volatile(
        "mma.sync.aligned.m16n8k16.row.col.f32.bf16.bf16.f32 "
        "{%0,%1,%2,%3}, {%4,%5,%6,%7}, {%8,%9}, {%0,%1,%2,%3};"
        : "+f"(c[0]), "+f"(c[1]), "+f"(c[2]), "+f"(c[3])
        : "r"(a[0]), "r"(a[1]), "r"(a[2]), "r"(a[3]), "r"(b[0]), "r"(b[1]));
}

// ======================= GEMM1: Wh = h @ W (as R3) =======================
static constexpr int ROWB   = 80;
static constexpr int TILE_B = 128 * ROWB;
static constexpr int STAGE_B = 4 * TILE_B;
static constexpr int SMEM1_SZ = 2 * STAGE_B;      // 81920

template<int KCHUNKS>
__global__ void __launch_bounds__(256, 1) mma_gemm1(
    const __nv_bfloat16* __restrict__ Ahi, const __nv_bfloat16* __restrict__ Alo,
    const __nv_bfloat16* __restrict__ Bhi, const __nv_bfloat16* __restrict__ Blo,
    __nv_bfloat16* __restrict__ ThiOut, __nv_bfloat16* __restrict__ TloOut)
{
    constexpr int K = KCHUNKS * 32;
    extern __shared__ char smem[];
    const uint32_t sb = smem_u32(smem);

    const int tid  = threadIdx.x;
    const int warp = tid >> 5;
    const int lane = tid & 31;
    const int wm   = warp & 3;
    const int wn   = warp >> 2;
    const int row0 = blockIdx.x * 128;
    const int col0 = blockIdx.y * 128;

    const int a_row = lane & 15;
    const int a_kb  = (lane >> 4) * 16;
    const int b_row = ((lane >> 4) << 3) + (lane & 7);
    const int b_kb  = ((lane >> 3) & 1) * 16;
    const int lrow = tid >> 2;
    const int lch  = tid & 3;

    float acc[2][8][4];
    #pragma unroll
    for (int i = 0; i < 2; i++)
        #pragma unroll
        for (int j = 0; j < 8; j++)
            #pragma unroll
            for (int q = 0; q < 4; q++) acc[i][j][q] = 0.0f;

    auto load_stage = [&](int s, int kc) {
        const uint32_t base = sb + s * STAGE_B;
        const int k0 = kc * 32;
        #pragma unroll
        for (int it = 0; it < 2; it++) {
            int r = lrow + it * 64;
            uint32_t doff = r * ROWB + lch * 16;
            size_t ga = (size_t)(row0 + r) * K + k0 + lch * 8;
            size_t gb = (size_t)(col0 + r) * K + k0 + lch * 8;
            cp_async16(base + 0 * TILE_B + doff, Ahi + ga);
            cp_async16(base + 1 * TILE_B + doff, Alo + ga);
            cp_async16(base + 2 * TILE_B + doff, Bhi + gb);
            cp_async16(base + 3 * TILE_B + doff, Blo + gb);
        }
        cp_commit();
    };

    load_stage(0, 0);

    for (int c = 0; c < KCHUNKS; c++) {
        const int s = c & 1;
        if (c + 1 < KCHUNKS) { load_stage(s ^ 1, c + 1); cp_wait<1>(); }
        else                 { cp_wait<0>(); }
        __syncthreads();

        const uint32_t base = sb + s * STAGE_B;
        #pragma unroll
        for (int ks = 0; ks < 2; ks++) {
            const int kb = ks * 32;
            uint32_t ah[2][4], al[2][4], bh[16], bl[16];
            #pragma unroll
            for (int mt = 0; mt < 2; mt++) {
                uint32_t ra = (wm * 32 + mt * 16 + a_row) * ROWB + kb + a_kb;
                ldm_x4(base + 0 * TILE_B + ra, ah[mt][0], ah[mt][1], ah[mt][2], ah[mt][3]);
                ldm_x4(base + 1 * TILE_B + ra, al[mt][0], al[mt][1], al[mt][2], al[mt][3]);
            }
            #pragma unroll
            for (int nb = 0; nb < 4; nb++) {
                uint32_t rb = (wn * 64 + nb * 16 + b_row) * ROWB + kb + b_kb;
                ldm_x4(base + 2 * TILE_B + rb, bh[4*nb], bh[4*nb+1], bh[4*nb+2], bh[4*nb+3]);
                ldm_x4(base + 3 * TILE_B + rb, bl[4*nb], bl[4*nb+1], bl[4*nb+2], bl[4*nb+3]);
            }
            #pragma unroll
            for (int mt = 0; mt < 2; mt++)
                #pragma unroll
                for (int nt = 0; nt < 8; nt++) {
                    mma_bf16(acc[mt][nt], ah[mt], bh + 2*nt);
                    mma_bf16(acc[mt][nt], ah[mt], bl + 2*nt);
                    mma_bf16(acc[mt][nt], al[mt], bh + 2*nt);
                }
        }
        __syncthreads();
    }

    // stage C^T bf16 hi/lo through smem, then coalesced store to [n][m]
    constexpr int TST = 272;
    __nv_bfloat16* shT = (__nv_bfloat16*)smem;
    __nv_bfloat16* slT = (__nv_bfloat16*)(smem + 128 * TST);
    #pragma unroll
    for (int mt = 0; mt < 2; mt++) {
        #pragma unroll
        for (int nt = 0; nt < 8; nt++) {
            int ml = wm * 32 + mt * 16 + (lane >> 2);
            int nl = wn * 64 + nt * 8 + (lane & 3) * 2;
            #pragma unroll
            for (int q = 0; q < 4; q++) {
                int m = ml + (q >> 1) * 8;
                int n = nl + (q & 1);
                float v = acc[mt][nt][q];
                __nv_bfloat16 hb = __float2bfloat16(v);
                __nv_bfloat16 lb = __float2bfloat16(v - __bfloat162float(hb));
                shT[n * 136 + m] = hb;
                slT[n * 136 + m] = lb;
            }
        }
    }
    __syncthreads();
    #pragma unroll
    for (int it = 0; it < 8; it++) {
        int idx = tid + it * 256;
        int n = idx >> 4, cm = idx & 15;
        uint4 vh = *(uint4*)(smem + n * TST + cm * 16);
        uint4 vl = *(uint4*)(smem + 128 * TST + n * TST + cm * 16);
        size_t g = (size_t)(col0 + n) * NN + row0 + cm * 8;
        *(uint4*)(ThiOut + g) = vh;
        *(uint4*)(TloOut + g) = vl;
    }
}

// ======================= fused softmax + P@Wh GEMM =======================
// CTA: 64 output rows x 256 cols, K = 8192 in 256 chunks of 32.
// A tile (p values) computed in-kernel from adj/f1/f2/cv; bf16 hi/lo 3-pass MMA.
static constexpr int F_BSTG   = 40960;                 // B stage: hi 20480 + lo 20480
static constexpr int F_OFF_B  = 0;
static constexpr int F_OFF_A  = 4 * F_BSTG;            // 163840 ; A hi 5120 + lo 5120
static constexpr int F_OFF_ADJ= F_OFF_A + 10240;       // 174080 ; 4 stages x 9216 (144B rows)
static constexpr int F_OFF_RS = F_OFF_ADJ + 4 * 9216;  // 210944
static constexpr int SMEM2_SZ = F_OFF_RS + 256;        // 211200

__global__ void __launch_bounds__(256, 1) fused_gemm2(
    const int* __restrict__ adj, const float* __restrict__ cv,
    float* __restrict__ out)
{
    extern __shared__ char smem[];
    const uint32_t sb = smem_u32(smem);
    const int tid  = threadIdx.x;
    const int warp = tid >> 5;
    const int lane = tid & 31;
    const int wm   = warp & 1;           // 2 row-warps (32 rows each)
    const int wn   = warp >> 1;          // 4 col-warps (64 cols each)
    const int row0 = blockIdx.x * 64;

    const int a_row = lane & 15;
    const int a_kb  = (lane >> 4) * 16;
    const int b_row = ((lane >> 4) << 3) + (lane & 7);
    const int b_kb  = ((lane >> 3) & 1) * 16;

    const int r_loc = tid >> 2;          // 0..63 : row this thread produces p for
    const int kq    = tid & 3;           // 8-col slice within chunk

    auto load_stage = [&](int slot, int c) {
        if (c < 256) {
            const int k0 = c * 32;
            const uint32_t bb = sb + F_OFF_B + slot * F_BSTG;
            #pragma unroll
            for (int it = 0; it < 4; it++) {
                int n = r_loc + it * 64;
                uint32_t off = n * 80 + kq * 16;
                size_t g = (size_t)n * NN + k0 + kq * 8;
                cp_async16(bb + off,         g_WhThi + g);
                cp_async16(bb + 20480 + off, g_WhTlo + g);
            }
            const uint32_t ab = sb + F_OFF_ADJ + slot * 9216;
            #pragma unroll
            for (int it = 0; it < 2; it++) {
                int idx = tid + it * 256;
                int r = idx >> 3, ch = idx & 7;
                cp_async16(ab + r * 144 + ch * 16,
                           adj + (size_t)(row0 + r) * NN + k0 + ch * 4);
            }
        }
        cp_commit();
    };

    // per-row constants + f2 register prefetch
    const float f1r   = g_f1[row0 + r_loc];
    const float biasr = THETA * cv[row0 + r_loc];
    float4 f2c0 = *(const float4*)(g_f2 + kq * 8);
    float4 f2c1 = *(const float4*)(g_f2 + kq * 8 + 4);
    float psum = 0.0f;

    float acc[2][8][4];
    #pragma unroll
    for (int i = 0; i < 2; i++)
        #pragma unroll
        for (int j = 0; j < 8; j++)
            #pragma unroll
            for (int q = 0; q < 4; q++) acc[i][j][q] = 0.0f;

    load_stage(0, 0);
    load_stage(1, 1);
    load_stage(2, 2);

    for (int c = 0; c < 256; c++) {
        const int s = c & 3;

        float4 f2n0, f2n1;
        if (c + 1 < 256) {
            f2n0 = *(const float4*)(g_f2 + (c + 1) * 32 + kq * 8);
            f2n1 = *(const float4*)(g_f2 + (c + 1) * 32 + kq * 8 + 4);
        } else { f2n0 = f2c0; f2n1 = f2c1; }

        cp_wait<2>();
        __syncthreads();

        // ---- compute p chunk -> A smem (bf16 hi/lo) ----
        {
            const char* ap = smem + F_OFF_ADJ + s * 9216 + r_loc * 144 + kq * 32;
            int4 av0 = ((const int4*)ap)[0];
            int4 av1 = ((const int4*)ap)[1];
            float f2v[8] = { f2c0.x, f2c0.y, f2c0.z, f2c0.w,
                             f2c1.x, f2c1.y, f2c1.z, f2c1.w };
            int m[8] = { av0.x, av0.y, av0.z, av0.w, av1.x, av1.y, av1.z, av1.w };
            float p[8];
            #pragma unroll
            for (int i = 0; i < 8; i++) {
                float e = f1r + f2v[i];
                e = e > 0.0f ? e : ALPHA_S * e;
                e += biasr;
                p[i] = m[i] > 0 ? __expf(e) : 0.0f;
                psum += p[i];
            }
            uint32_t hi[4], lo[4];
            #pragma unroll
            for (int i = 0; i < 4; i++) {
                __nv_bfloat16 h0 = __float2bfloat16(p[2*i]);
                __nv_bfloat16 h1 = __float2bfloat16(p[2*i+1]);
                __nv_bfloat162 hp(h0, h1);
                __nv_bfloat162 lp(__float2bfloat16(p[2*i]   - __bfloat162float(h0)),
                                  __float2bfloat16(p[2*i+1] - __bfloat162float(h1)));
                hi[i] = *(uint32_t*)&hp;
                lo[i] = *(uint32_t*)&lp;
            }
            char* dst = smem + F_OFF_A + r_loc * 80 + kq * 16;
            *(uint4*)dst          = make_uint4(hi[0], hi[1], hi[2], hi[3]);
            *(uint4*)(dst + 5120) = make_uint4(lo[0], lo[1], lo[2], lo[3]);
        }
        __syncthreads();

        // ---- MMA on chunk c ----
        const uint32_t bbase = sb + F_OFF_B + s * F_BSTG;
        #pragma unroll
        for (int ks = 0; ks < 2; ks++) {
            const int kb = ks * 32;
            uint32_t ah[2][4], al[2][4], bh[16], bl[16];
            #pragma unroll
            for (int mt = 0; mt < 2; mt++) {
                uint32_t ra = sb + F_OFF_A + (wm * 32 + mt * 16 + a_row) * 80 + kb + a_kb;
                ldm_x4(ra,        ah[mt][0], ah[mt][1], ah[mt][2], ah[mt][3]);
                ldm_x4(ra + 5120, al[mt][0], al[mt][1], al[mt][2], al[mt][3]);
            }
            #pragma unroll
            for (int nb = 0; nb < 4; nb++) {
                uint32_t rb = bbase + (wn * 64 + nb * 16 + b_row) * 80 + kb + b_kb;
                ldm_x4(rb,         bh[4*nb], bh[4*nb+1], bh[4*nb+2], bh[4*nb+3]);
                ldm_x4(rb + 20480, bl[4*nb], bl[4*nb+1], bl[4*nb+2], bl[4*nb+3]);
            }
            #pragma unroll
            for (int mt = 0; mt < 2; mt++)
                #pragma unroll
                for (int nt = 0; nt < 8; nt++) {
                    mma_bf16(acc[mt][nt], ah[mt], bh + 2*nt);
                    mma_bf16(acc[mt][nt], ah[mt], bl + 2*nt);
                    mma_bf16(acc[mt][nt], al[mt], bh + 2*nt);
                }
        }
        __syncthreads();

        load_stage((c + 3) & 3, c + 3);
        f2c0 = f2n0; f2c1 = f2n1;
    }

    // ---- rowsum reduce (4 threads per row, contiguous lanes) ----
    psum += __shfl_xor_sync(0xffffffffu, psum, 1);
    psum += __shfl_xor_sync(0xffffffffu, psum, 2);
    if ((tid & 3) == 0) *(float*)(smem + F_OFF_RS + r_loc * 4) = psum;
    __syncthreads();
    const float* rs = (const float*)(smem + F_OFF_RS);

    // ---- epilogue: out = elu(acc / rowsum) ----
    #pragma unroll
    for (int mt = 0; mt < 2; mt++) {
        int rAl = wm * 32 + mt * 16 + (lane >> 2);
        int rBl = rAl + 8;
        float invA = 1.0f / rs[rAl];
        float invB = 1.0f / rs[rBl];
        #pragma unroll
        for (int nt = 0; nt < 8; nt++) {
            int cc = wn * 64 + nt * 8 + (lane & 3) * 2;
            float v0 = acc[mt][nt][0] * invA;
            float v1 = acc[mt][nt][1] * invA;
            float v2 = acc[mt][nt][2] * invB;
            float v3 = acc[mt][nt][3] * invB;
            float2 oA = { v0 > 0.f ? v0 : expm1f(v0), v1 > 0.f ? v1 : expm1f(v1) };
            float2 oB = { v2 > 0.f ? v2 : expm1f(v2), v3 > 0.f ? v3 : expm1f(v3) };
            *(float2*)(out + (size_t)(row0 + rAl) * FD + cc) = oA;
            *(float2*)(out + (size_t)(row0 + rBl) * FD + cc) = oB;
        }
    }
}

// ---------------- input conversion ----------------
__global__ void convert_kernel(const float* __restrict__ h, const float* __restrict__ W)
{
    int t = blockIdx.x * 256 + threadIdx.x;
    if (blockIdx.x < NN) {
        float v = h[t];
        __nv_bfloat16 hb = __float2bfloat16(v);
        g_hhi[t] = hb;
        g_hlo[t] = __float2bfloat16(v - __bfloat162float(hb));
    } else {
        int idx = t - NN * 256;
        int o = idx >> 8, i = idx & 255;
        float v = W[i * FD + o];
        __nv_bfloat16 hb = __float2bfloat16(v);
        g_WThi[idx] = hb;
        g_WTlo[idx] = __float2bfloat16(v - __bfloat162float(hb));
    }
}

// ---------------- f1/f2 from WhT splits ----------------
__global__ void f1f2_kernel(const float* __restrict__ a)
{
    int m = blockIdx.x * 256 + threadIdx.x;
    float s1 = 0.0f, s2 = 0.0f;
    #pragma unroll 4
    for (int n = 0; n < FD; n++) {
        float v = __bfloat162float(g_WhThi[(size_t)n * NN + m]) +
                  __bfloat162float(g_WhTlo[(size_t)n * NN + m]);
        s1 = fmaf(v, __ldg(a + n),      s1);
        s2 = fmaf(v, __ldg(a + FD + n), s2);
    }
    g_f1[m] = s1;
    g_f2[m] = s2;
}

// ---------------- launch ----------------
extern "C" void kernel_launch(void* const* d_in, const int* in_sizes, int n_in,
                              void* d_out, int out_size)
{
    const float* h   = (const float*)d_in[0];
    const int*   adj = (const int*)  d_in[1];
    const float* cv  = (const float*)d_in[2];
    const float* W   = (const float*)d_in[3];
    const float* a   = (const float*)d_in[4];
    float* out = (float*)d_out;

    __nv_bfloat16 *phhi, *phlo, *pWThi, *pWTlo, *pWhThi, *pWhTlo;
    cudaGetSymbolAddress((void**)&phhi,   g_hhi);
    cudaGetSymbolAddress((void**)&phlo,   g_hlo);
    cudaGetSymbolAddress((void**)&pWThi,  g_WThi);
    cudaGetSymbolAddress((void**)&pWTlo,  g_WTlo);
    cudaGetSymbolAddress((void**)&pWhThi, g_WhThi);
    cudaGetSymbolAddress((void**)&pWhTlo, g_WhTlo);

    cudaFuncSetAttribute(mma_gemm1<8>, cudaFuncAttributeMaxDynamicSharedMemorySize, SMEM1_SZ);
    cudaFuncSetAttribute(fused_gemm2,  cudaFuncAttributeMaxDynamicSharedMemorySize, SMEM2_SZ);

    // 1) bf16 hi/lo splits of h and W^T
    convert_kernel<<<NN + FD, 256>>>(h, W);

    // 2) Wh = h@W; epilogue writes WhT hi/lo
    {
        dim3 grid(NN / 128, FD / 128);
        mma_gemm1<8><<<grid, 256, SMEM1_SZ>>>(
            phhi, phlo, pWThi, pWTlo, pWhThi, pWhTlo);
    }

    // 3) f1/f2
    f1f2_kernel<<<NN / 256, 256>>>(a);

    // 4) fused masked-softmax + (P @ Wh)/rowsum + ELU
    fused_gemm2<<<NN / 64, 256, SMEM2_SZ>>>(adj, cv, out);
}